// round 2
// baseline (speedup 1.0000x reference)
#include <cuda_runtime.h>
#include <cuda_bf16.h>

// Fused 2-layer RNN (hidden=1), S=2048, B=256, I=128.
//   xp[s,b] = x[s,b,:] . W_ih0 + b_ih0 + b_hh0          (producer CTAs, HBM-bound)
//   h1 = tanh(xp + h1*W_hh0); h2 = tanh(h1*W_ih1 + b1 + h2*W_hh1)   (consumer CTAs)
//   out[b] = sigmoid(h2[S-1,b])
//
// Single kernel: 140 producer CTAs stream the projection round-robin over
// timesteps and publish per-step flags (release); 8 consumer CTAs (1 warp
// each) run the recurrence chasing the flags (acquire), double-buffered two
// 16-step chunks ahead so polls and L2 latency stay off the tanh chain.

#define S_LEN  2048
#define B_SZ   256
#define I_SZ   128
#define NPROD  140
#define NCONS  8
#define NCTA   (NPROD + NCONS)
#define CHUNK  16
#define NCHUNK (S_LEN / CHUNK)   // 128

__device__ float    g_xp[S_LEN * B_SZ];      // projected inputs, [s][b]
__device__ unsigned g_flag[S_LEN + 4 * CHUNK]; // per-step ready flags (+pad for prefetch overrun)
__device__ unsigned g_done;                  // consumer-CTA completion counter

__device__ __forceinline__ float tanh_fast(float x) {
    float y;
    asm("tanh.approx.f32 %0, %1;" : "=f"(y) : "f"(x));
    return y;
}

__device__ __forceinline__ unsigned ldacq(const unsigned* p) {
    unsigned v;
    asm volatile("ld.acquire.gpu.global.u32 %0, [%1];" : "=r"(v) : "l"(p) : "memory");
    return v;
}

__device__ __forceinline__ void strel(unsigned* p, unsigned v) {
    asm volatile("st.release.gpu.global.u32 [%0], %1;" :: "l"(p), "r"(v) : "memory");
}

// One pipelined recurrence step: computes h1_j and h2_{j-1}.
// Both FFMAs issue before the MUFUs -> steady-state period ~22 cyc.
#define STEP(xv) do {                    \
    float p1_ = fmaf(h1, w00, (xv));     \
    float p2_ = fmaf(h2, d1, sv);        \
    h1 = tanh_fast(p1_);                 \
    h2 = tanh_fast(p2_);                 \
    sv = fmaf(h1, a1, c1);               \
} while (0)

__global__ __launch_bounds__(256) void rnn_fused(
    const float* __restrict__ x,
    const float* __restrict__ w_ih0,
    const float* __restrict__ w_hh0,
    const float* __restrict__ b_ih0,
    const float* __restrict__ b_hh0,
    const float* __restrict__ w_ih1,
    const float* __restrict__ w_hh1,
    const float* __restrict__ b_ih1,
    const float* __restrict__ b_hh1,
    float* __restrict__ out)
{
    const int cta = blockIdx.x;

    if (cta < NPROD) {
        // ------------------------- PRODUCER -------------------------
        // Timestep s handled by CTA s % NPROD. Per timestep: 256 rows,
        // warp per 32 consecutive rows, lane per float4 of the row.
        const int wid  = threadIdx.x >> 5;
        const int lane = threadIdx.x & 31;
        const float bias = b_ih0[0] + b_hh0[0];
        const float4 wv = reinterpret_cast<const float4*>(w_ih0)[lane];
        const float4* __restrict__ x4 = reinterpret_cast<const float4*>(x);

        for (int s = cta; s < S_LEN; s += NPROD) {
            const int rowbase = s * B_SZ + wid * 32;
            #pragma unroll 2
            for (int i = 0; i < 32; i += 4) {
                float4 xa = x4[(size_t)(rowbase + i + 0) * 32 + lane];
                float4 xb = x4[(size_t)(rowbase + i + 1) * 32 + lane];
                float4 xc = x4[(size_t)(rowbase + i + 2) * 32 + lane];
                float4 xd = x4[(size_t)(rowbase + i + 3) * 32 + lane];

                float sa = fmaf(xa.x, wv.x, fmaf(xa.y, wv.y, fmaf(xa.z, wv.z, xa.w * wv.w)));
                float sb = fmaf(xb.x, wv.x, fmaf(xb.y, wv.y, fmaf(xb.z, wv.z, xb.w * wv.w)));
                float sc = fmaf(xc.x, wv.x, fmaf(xc.y, wv.y, fmaf(xc.z, wv.z, xc.w * wv.w)));
                float sd = fmaf(xd.x, wv.x, fmaf(xd.y, wv.y, fmaf(xd.z, wv.z, xd.w * wv.w)));

                #pragma unroll
                for (int o = 16; o; o >>= 1) {
                    sa += __shfl_xor_sync(0xffffffffu, sa, o);
                    sb += __shfl_xor_sync(0xffffffffu, sb, o);
                    sc += __shfl_xor_sync(0xffffffffu, sc, o);
                    sd += __shfl_xor_sync(0xffffffffu, sd, o);
                }
                if (lane == 0) {
                    float4 r = make_float4(sa + bias, sb + bias, sc + bias, sd + bias);
                    *reinterpret_cast<float4*>(&g_xp[rowbase + i]) = r;
                }
            }
            __syncthreads();                 // all 256 rows of step s stored
            if (threadIdx.x == 0)
                strel(&g_flag[s], 1u);       // publish step s
        }
        return;
    }

    // ------------------------- CONSUMER -------------------------
    if (threadIdx.x >= 32) return;           // one warp per consumer CTA
    const int b = (cta - NPROD) * 32 + threadIdx.x;

    const float w00 = w_hh0[0];
    const float a1  = w_ih1[0];
    const float d1  = w_hh1[0];
    const float c1  = b_ih1[0] + b_hh1[0];

    float h1 = 0.0f, h2 = 0.0f, sv = 0.0f;   // sv=0,h2=0 => pipelined h2_{-1}=0
    float cur[CHUNK], nxt[CHUNK];
    unsigned fl[CHUNK];

    const float* __restrict__ xp = g_xp;

    // --- prologue: chunk 0 into cur, chunk 1 into nxt, flags(chunk2) in flight
    {
        unsigned ok;
        do {                                  // wait chunk 0 ready
            #pragma unroll
            for (int j = 0; j < CHUNK; j++) fl[j] = ldacq(&g_flag[j]);
            ok = fl[0];
            #pragma unroll
            for (int j = 1; j < CHUNK; j++) ok &= fl[j];
        } while (!ok);
        #pragma unroll
        for (int j = 0; j < CHUNK; j++) cur[j] = xp[j * B_SZ + b];

        do {                                  // wait chunk 1 ready
            #pragma unroll
            for (int j = 0; j < CHUNK; j++) fl[j] = ldacq(&g_flag[CHUNK + j]);
            ok = fl[0];
            #pragma unroll
            for (int j = 1; j < CHUNK; j++) ok &= fl[j];
        } while (!ok);
        #pragma unroll
        for (int j = 0; j < CHUNK; j++) nxt[j] = xp[(CHUNK + j) * B_SZ + b];

        #pragma unroll
        for (int j = 0; j < CHUNK; j++) fl[j] = ldacq(&g_flag[2 * CHUNK + j]);
    }

    // --- main loop: body c consumes chunk c, prepares chunk c+2
    for (int c = 0; c < NCHUNK - 2; c++) {
        #pragma unroll
        for (int j = 0; j < CHUNK; j++) STEP(cur[j]);

        // verify flags for chunk c+2 (loads were issued a full chunk ago)
        unsigned ok = fl[0];
        #pragma unroll
        for (int j = 1; j < CHUNK; j++) ok &= fl[j];
        while (!ok) {
            const int fbase = (c + 2) * CHUNK;
            #pragma unroll
            for (int j = 0; j < CHUNK; j++) fl[j] = ldacq(&g_flag[fbase + j]);
            ok = fl[0];
            #pragma unroll
            for (int j = 1; j < CHUNK; j++) ok &= fl[j];
        }

        #pragma unroll
        for (int j = 0; j < CHUNK; j++) cur[j] = nxt[j];   // waits chunk c+1 loads

        const int sbase = (c + 2) * CHUNK;
        #pragma unroll
        for (int j = 0; j < CHUNK; j++) nxt[j] = xp[(sbase + j) * B_SZ + b];

        const int fbase = (c + 3) * CHUNK;                 // pad covers c+3==128
        #pragma unroll
        for (int j = 0; j < CHUNK; j++) fl[j] = ldacq(&g_flag[fbase + j]);
    }

    // --- epilogue: chunks 126 and 127
    #pragma unroll
    for (int j = 0; j < CHUNK; j++) STEP(cur[j]);
    #pragma unroll
    for (int j = 0; j < CHUNK; j++) cur[j] = nxt[j];
    #pragma unroll
    for (int j = 0; j < CHUNK; j++) STEP(cur[j]);

    h2 = tanh_fast(fmaf(h2, d1, sv));        // recover h2_{S-1}
    out[b] = 1.0f / (1.0f + __expf(-h2));

    // --- cleanup: last consumer CTA zeroes flags + counter for graph replays
    __syncwarp();
    unsigned last = 0;
    if (threadIdx.x == 0) {
        asm volatile("fence.acq_rel.gpu;" ::: "memory");
        last = (atomicAdd(&g_done, 1u) == NCONS - 1) ? 1u : 0u;
    }
    last = __shfl_sync(0xffffffffu, last, 0);
    if (last) {
        asm volatile("fence.acq_rel.gpu;" ::: "memory");
        for (int i = threadIdx.x; i < S_LEN + 4 * CHUNK; i += 32)
            g_flag[i] = 0u;
        if (threadIdx.x == 0) g_done = 0u;
    }
}

extern "C" void kernel_launch(void* const* d_in, const int* in_sizes, int n_in,
                              void* d_out, int out_size)
{
    const float* x    = (const float*)d_in[0];
    const float* Wih0 = (const float*)d_in[1];
    const float* Whh0 = (const float*)d_in[2];
    const float* bih0 = (const float*)d_in[3];
    const float* bhh0 = (const float*)d_in[4];
    const float* Wih1 = (const float*)d_in[5];
    const float* Whh1 = (const float*)d_in[6];
    const float* bih1 = (const float*)d_in[7];
    const float* bhh1 = (const float*)d_in[8];
    float* out = (float*)d_out;

    rnn_fused<<<NCTA, 256>>>(x, Wih0, Whh0, bih0, bhh0,
                             Wih1, Whh1, bih1, bhh1, out);
}